// round 13
// baseline (speedup 1.0000x reference)
#include <cuda_runtime.h>
#include <cuda_fp16.h>
#include <cstdint>

#define BATCHN 128
#define TLEN   256
#define DM     384
#define NH     6
#define HS     64
#define FFD    1536
#define MROWS  (BATCHN*TLEN)   // 32768
#define QKVN   (3*DM)          // 1152

// ---------------- scratch (device globals: allocation-free rule) ----------------
__device__ __align__(256) __half g_h   [MROWS*DM];
__device__ __align__(256) __half g_qkv [MROWS*QKVN];
__device__ __align__(256) __half g_attn[MROWS*DM];
__device__ __align__(256) float  g_x2  [MROWS*DM];     // residual kept f32
__device__ __align__(256) __half g_h2  [MROWS*DM];
__device__ __align__(256) __half g_ff1 [MROWS*FFD];
__device__ __align__(256) __half g_Wqkv[QKVN*DM];      // [n][k]
__device__ __align__(256) __half g_Wp  [DM*DM];
__device__ __align__(256) __half g_W1  [FFD*DM];
__device__ __align__(256) __half g_W2  [DM*FFD];

// ---------------- helpers ----------------
__device__ __forceinline__ uint32_t s2u(const void* p) {
    return (uint32_t)__cvta_generic_to_shared(p);
}
#define CP16(dst, src) asm volatile("cp.async.cg.shared.global [%0],[%1],16;\n" :: "r"(dst), "l"(src))
#define CPCOMMIT()     asm volatile("cp.async.commit_group;\n")
#define CPWAIT(n)      asm volatile("cp.async.wait_group %0;\n" :: "n"(n))
#define LDSM4(r0,r1,r2,r3,addr) \
    asm volatile("ldmatrix.sync.aligned.m8n8.x4.shared.b16 {%0,%1,%2,%3},[%4];" \
                 : "=r"(r0),"=r"(r1),"=r"(r2),"=r"(r3) : "r"(addr))
#define LDSM4T(r0,r1,r2,r3,addr) \
    asm volatile("ldmatrix.sync.aligned.m8n8.x4.trans.shared.b16 {%0,%1,%2,%3},[%4];" \
                 : "=r"(r0),"=r"(r1),"=r"(r2),"=r"(r3) : "r"(addr))

__device__ __forceinline__ void mma16816(float* c, uint32_t a0, uint32_t a1,
                                         uint32_t a2, uint32_t a3,
                                         uint32_t b0, uint32_t b1) {
    asm volatile(
        "mma.sync.aligned.m16n8k16.row.col.f32.f16.f16.f32 "
        "{%0,%1,%2,%3},{%4,%5,%6,%7},{%8,%9},{%0,%1,%2,%3};\n"
        : "+f"(c[0]), "+f"(c[1]), "+f"(c[2]), "+f"(c[3])
        : "r"(a0), "r"(a1), "r"(a2), "r"(a3), "r"(b0), "r"(b1));
}

// pack two floats into one u32 holding half2 (full 32 bits)
__device__ __forceinline__ uint32_t pack_h2(float a, float b) {
    __half2 h = __floats2half2_rn(a, b);
    uint32_t u;
    asm("mov.b32 %0, %1;" : "=r"(u) : "r"(*(uint32_t*)&h));
    return u;
}

// ---------------- weight packing (split: qkv first, rest second) ----------------
__global__ void pack_qkv_k(const float* __restrict__ Wq, const float* __restrict__ Wk,
                           const float* __restrict__ Wv) {
    int idx = blockIdx.x * 256 + threadIdx.x;
    if (idx >= QKVN * DM) return;
    int n = idx / DM, k = idx - n * DM;
    int part = n / DM, c = n - part * DM;
    int h = c >> 6, e = c & 63;
    const float* W = (part == 0) ? Wq : (part == 1) ? Wk : Wv;
    g_Wqkv[idx] = __float2half(W[(h * DM + k) * HS + e]);
}
__global__ void pack_rest_k(const float* __restrict__ Wp, const float* __restrict__ W1,
                            const float* __restrict__ W2) {
    int idx = blockIdx.x * 256 + threadIdx.x;
    const int n1 = DM * DM;
    const int n2 = n1 + FFD * DM;
    const int n3 = n2 + DM * FFD;
    if (idx < n1) {
        int n = idx / DM, k = idx - n * DM;
        g_Wp[idx] = __float2half(Wp[k * DM + n]);
    } else if (idx < n2) {
        int i = idx - n1;
        int n = i / DM, k = i - n * DM;
        g_W1[i] = __float2half(W1[k * FFD + n]);
    } else if (idx < n3) {
        int i = idx - n2;
        int n = i / FFD, k = i - n * FFD;
        g_W2[i] = __float2half(W2[k * DM + n]);
    }
}

// ---------------- LayerNorm: warp per row, f32 in -> half out ----------------
template <int SRC>
__global__ void __launch_bounds__(256) ln_k(const float* __restrict__ xin,
                                            const float* __restrict__ gam,
                                            const float* __restrict__ bet) {
    const float* x = (SRC == 0) ? xin : g_x2;
    __half* out = (SRC == 0) ? g_h : g_h2;
    int row = blockIdx.x * 8 + (threadIdx.x >> 5);
    int lane = threadIdx.x & 31;
    const float* xr = x + (size_t)row * DM;
    float v[12];
    float s = 0.f;
#pragma unroll
    for (int i = 0; i < 12; i++) { v[i] = xr[lane + 32 * i]; s += v[i]; }
#pragma unroll
    for (int o = 16; o; o >>= 1) s += __shfl_xor_sync(0xffffffffu, s, o);
    float mu = s * (1.f / DM);
    float var = 0.f;
#pragma unroll
    for (int i = 0; i < 12; i++) { float d = v[i] - mu; var += d * d; }
#pragma unroll
    for (int o = 16; o; o >>= 1) var += __shfl_xor_sync(0xffffffffu, var, o);
    float r = rsqrtf(var * (1.f / DM) + 1e-5f);
    __half* orow = out + (size_t)row * DM;
#pragma unroll
    for (int i = 0; i < 12; i++) {
        int c = lane + 32 * i;
        orow[c] = __float2half((v[i] - mu) * r * gam[c] + bet[c]);
    }
}

// ---------------- fp16 GEMM: CTA 256x128, 256 thr, warp tile 64x64, BK=64, 2-stage ----
#define SW 72                         // smem row stride in halves (9x16B: conflict-free)
#define A_STG (256 * SW * 2)          // 36864
#define B_STG (128 * SW * 2)          // 18432
#define GEMM_SMEM (2 * (A_STG + B_STG))   // 110592

template <int CFG>
__device__ __forceinline__ void epi_store(int row, int col, float v0, float v1,
                                          const float* __restrict__ bias,
                                          const float* __restrict__ resid,
                                          float* __restrict__ outp, int N) {
    size_t o = (size_t)row * N + col;
    if (CFG == 0) {
        *(__half2*)(g_qkv + o) = __floats2half2_rn(v0, v1);
    } else if (CFG == 1) {
        float2 r = *(const float2*)(resid + o);
        *(float2*)(g_x2 + o) = make_float2(v0 + bias[col] + r.x, v1 + bias[col + 1] + r.y);
    } else if (CFG == 2) {
        *(__half2*)(g_ff1 + o) = __floats2half2_rn(fmaxf(v0 + bias[col], 0.f),
                                                   fmaxf(v1 + bias[col + 1], 0.f));
    } else {
        float2 r = *(const float2*)(g_x2 + o);
        *(float2*)(outp + o) = make_float2(v0 + bias[col] + r.x, v1 + bias[col + 1] + r.y);
    }
}

template <int CFG>
__global__ void __launch_bounds__(256, 1)
gemm_k(const float* __restrict__ bias, const float* __restrict__ resid,
       float* __restrict__ outp) {
    constexpr int N = (CFG == 0) ? QKVN : (CFG == 2) ? FFD : DM;
    constexpr int K = (CFG == 3) ? FFD : DM;
    constexpr int NT = K / 64;        // 6 or 24
    const __half* __restrict__ A = (CFG == 0) ? g_h : (CFG == 1) ? g_attn
                                 : (CFG == 2) ? g_h2 : g_ff1;
    const __half* __restrict__ W = (CFG == 0) ? g_Wqkv : (CFG == 1) ? g_Wp
                                 : (CFG == 2) ? g_W1 : g_W2;

    extern __shared__ __half sm[];
    uint32_t aBase = s2u(sm);
    uint32_t bBase = aBase + 2 * A_STG;

    int tid = threadIdx.x;
    int lane = tid & 31, wid = tid >> 5;     // 8 warps
    int wm = wid & 3, wn = wid >> 2;         // 4 warps along M (64 each), 2 along N (64 each)
    int m0 = blockIdx.y * 256, n0 = blockIdx.x * 128;

    auto LOAD = [&](int kt) {
        int st = kt & 1;
        uint32_t aS = aBase + st * A_STG;
        uint32_t bS = bBase + st * B_STG;
#pragma unroll
        for (int i = 0; i < 8; i++) {        // A: 2048 16B chunks
            int c = tid + 256 * i;
            int row = c >> 3, col = (c & 7) * 8;
            CP16(aS + (uint32_t)(row * SW + col) * 2,
                 A + (size_t)(m0 + row) * K + kt * 64 + col);
        }
#pragma unroll
        for (int i = 0; i < 4; i++) {        // B: 1024 16B chunks
            int c = tid + 256 * i;
            int row = c >> 3, col = (c & 7) * 8;
            CP16(bS + (uint32_t)(row * SW + col) * 2,
                 W + (size_t)(n0 + row) * K + kt * 64 + col);
        }
        CPCOMMIT();
    };

    float acc[4][8][4];
#pragma unroll
    for (int a = 0; a < 4; a++)
#pragma unroll
        for (int b = 0; b < 8; b++)
#pragma unroll
            for (int c = 0; c < 4; c++) acc[a][b][c] = 0.f;

    LOAD(0);

    int l15 = lane & 15;
    int colb = (lane >> 4) * 8;

    for (int kt = 0; kt < NT; kt++) {
        if (kt + 1 < NT) { LOAD(kt + 1); CPWAIT(1); }
        else             { CPWAIT(0); }
        __syncthreads();

        uint32_t aS = aBase + (kt & 1) * A_STG;
        uint32_t bS = bBase + (kt & 1) * B_STG;
#pragma unroll
        for (int kk = 0; kk < 64; kk += 16) {
            uint32_t af[4][4], bf[8][2];
#pragma unroll
            for (int mt = 0; mt < 4; mt++) {
                int r = wm * 64 + mt * 16 + l15;
                LDSM4(af[mt][0], af[mt][1], af[mt][2], af[mt][3],
                      aS + (r * SW + kk + colb) * 2);
            }
#pragma unroll
            for (int np = 0; np < 4; np++) {
                uint32_t r0, r1, r2, r3;
                int r = wn * 64 + np * 16 + l15;
                LDSM4(r0, r1, r2, r3, bS + (r * SW + kk + colb) * 2);
                bf[2 * np][0] = r0; bf[2 * np + 1][0] = r1;
                bf[2 * np][1] = r2; bf[2 * np + 1][1] = r3;
            }
#pragma unroll
            for (int mt = 0; mt < 4; mt++)
#pragma unroll
                for (int nt = 0; nt < 8; nt++)
                    mma16816(acc[mt][nt], af[mt][0], af[mt][1], af[mt][2], af[mt][3],
                             bf[nt][0], bf[nt][1]);
        }
        __syncthreads();   // all warps done reading this slot before it is overwritten
    }

    int g = lane >> 2, tg = lane & 3;
#pragma unroll
    for (int mt = 0; mt < 4; mt++)
#pragma unroll
        for (int nt = 0; nt < 8; nt++) {
            int row = m0 + wm * 64 + mt * 16 + g;
            int col = n0 + wn * 64 + nt * 8 + tg * 2;
            epi_store<CFG>(row, col, acc[mt][nt][0], acc[mt][nt][1], bias, resid, outp, N);
            epi_store<CFG>(row + 8, col, acc[mt][nt][2], acc[mt][nt][3], bias, resid, outp, N);
        }
}

// ---------------- attention: mma-based flash-style (R8 passing version) ----------------
#define AS_V (256*72)
#define AS_Q (AS_V + 256*72)
#define AS_HALVES (AS_Q + 64*72)
#define AS_OSM (AS_HALVES * 2)
#define AS_SM  (AS_OSM + 4*16*66*4)
#define AS_SS  (AS_SM + 512)
#define ATTN_SMEM (AS_SS + 512)            // 100864

__global__ void __launch_bounds__(256, 2) attn_k() {
    extern __shared__ unsigned char smraw[];
    __half* sK = (__half*)smraw;
    __half* sV = sK + AS_V;
    __half* sQ = sK + AS_Q;
    float* Osm = (float*)(smraw + AS_OSM);
    float* sM  = (float*)(smraw + AS_SM);
    float* sS  = (float*)(smraw + AS_SS);

    int bh = blockIdx.x;
    int b = bh / NH, h = bh - b * NH;
    int tid = threadIdx.x, wid = tid >> 5, lane = tid & 31;
    int wm = wid & 3, ch = wid >> 2;
    int g = lane >> 2, tg = lane & 3;
    int l15 = lane & 15;
    int colb = (lane >> 4) * 8;
    const __half* base = g_qkv + (size_t)b * TLEN * QKVN;

    for (int i = tid; i < TLEN * 32; i += 256) {
        int s = i >> 5, e2 = i & 31;
        ((__half2*)sK)[s * 36 + e2] =
            *(const __half2*)(base + (size_t)s * QKVN + DM + h * HS + 2 * e2);
        ((__half2*)sV)[s * 36 + e2] =
            *(const __half2*)(base + (size_t)s * QKVN + 2 * DM + h * HS + 2 * e2);
    }
    __syncthreads();

    uint32_t kB = s2u(sK), vB = s2u(sV), qB = s2u(sQ);
    const __half2 qscale = __floats2half2_rn(0.125f, 0.125f);
    int stIdx = (ch * 4 + wm) * 16;
    int stOth = ((1 - ch) * 4 + wm) * 16;

    for (int iq = 0; iq < 4; iq++) {
        int tq = iq * 64;
        for (int i = tid; i < 64 * 32; i += 256) {
            int r = i >> 5, e2 = i & 31;
            __half2 q2 = *(const __half2*)(base + (size_t)(tq + r) * QKVN + h * HS + 2 * e2);
            ((__half2*)sQ)[r * 36 + e2] = __hmul2(q2, qscale);
        }
        __syncthreads();

        int lim = tq + wm * 16 + 15;
        int row1 = tq + wm * 16 + g, row2 = row1 + 8;

        float acc[16][4];
#pragma unroll
        for (int nt = 0; nt < 16; nt++)
#pragma unroll
            for (int c = 0; c < 4; c++) acc[nt][c] = 0.f;

#pragma unroll
        for (int kt = 0; kt < 4; kt++) {
            uint32_t a0, a1, a2, a3;
            LDSM4(a0, a1, a2, a3, qB + ((wm * 16 + l15) * 72 + kt * 16 + colb) * 2);
#pragma unroll
            for (int ntp = 0; ntp < 8; ntp++) {
                int nb = ch * 128 + ntp * 16;
                if (nb <= lim) {
                    uint32_t r0, r1, r2, r3;
                    LDSM4(r0, r1, r2, r3, kB + ((nb + l15) * 72 + kt * 16 + colb) * 2);
                    mma16816(acc[2 * ntp],     a0, a1, a2, a3, r0, r2);
                    mma16816(acc[2 * ntp + 1], a0, a1, a2, a3, r1, r3);
                }
            }
        }

#pragma unroll
        for (int nt = 0; nt < 16; nt++) {
            int c0 = ch * 128 + nt * 8 + tg * 2;
            if (c0 > row1)     acc[nt][0] = -1e30f;
            if (c0 + 1 > row1) acc[nt][1] = -1e30f;
            if (c0 > row2)     acc[nt][2] = -1e30f;
            if (c0 + 1 > row2) acc[nt][3] = -1e30f;
        }

        float m1 = -1e30f, m2 = -1e30f;
#pragma unroll
        for (int nt = 0; nt < 16; nt++) {
            m1 = fmaxf(m1, fmaxf(acc[nt][0], acc[nt][1]));
            m2 = fmaxf(m2, fmaxf(acc[nt][2], acc[nt][3]));
        }
        m1 = fmaxf(m1, __shfl_xor_sync(0xffffffffu, m1, 1));
        m1 = fmaxf(m1, __shfl_xor_sync(0xffffffffu, m1, 2));
        m2 = fmaxf(m2, __shfl_xor_sync(0xffffffffu, m2, 1));
        m2 = fmaxf(m2, __shfl_xor_sync(0xffffffffu, m2, 2));
        if (tg == 0) { sM[stIdx + g] = m1; sM[stIdx + g + 8] = m2; }
        __syncthreads();
        float M1 = fmaxf(m1, sM[stOth + g]);
        float M2 = fmaxf(m2, sM[stOth + g + 8]);

        float s1 = 0.f, s2 = 0.f;
#pragma unroll
        for (int nt = 0; nt < 16; nt++) {
            acc[nt][0] = __expf(acc[nt][0] - M1);
            acc[nt][1] = __expf(acc[nt][1] - M1);
            acc[nt][2] = __expf(acc[nt][2] - M2);
            acc[nt][3] = __expf(acc[nt][3] - M2);
            s1 += acc[nt][0] + acc[nt][1];
            s2 += acc[nt][2] + acc[nt][3];
        }
        s1 += __shfl_xor_sync(0xffffffffu, s1, 1);
        s1 += __shfl_xor_sync(0xffffffffu, s1, 2);
        s2 += __shfl_xor_sync(0xffffffffu, s2, 1);
        s2 += __shfl_xor_sync(0xffffffffu, s2, 2);
        if (tg == 0) { sS[stIdx + g] = s1; sS[stIdx + g + 8] = s2; }
        __syncthreads();
        float inv1 = 1.f / (s1 + sS[stOth + g]);
        float inv2 = 1.f / (s2 + sS[stOth + g + 8]);

        uint32_t pa[8][4];
#pragma unroll
        for (int kt = 0; kt < 8; kt++) {
            pa[kt][0] = pack_h2(acc[2 * kt][0],     acc[2 * kt][1]);
            pa[kt][1] = pack_h2(acc[2 * kt][2],     acc[2 * kt][3]);
            pa[kt][2] = pack_h2(acc[2 * kt + 1][0], acc[2 * kt + 1][1]);
            pa[kt][3] = pack_h2(acc[2 * kt + 1][2], acc[2 * kt + 1][3]);
        }

        float oa[8][4];
#pragma unroll
        for (int nt = 0; nt < 8; nt++)
#pragma unroll
            for (int c = 0; c < 4; c++) oa[nt][c] = 0.f;

#pragma unroll
        for (int kt = 0; kt < 8; kt++) {
            int sb = ch * 128 + kt * 16;
            if (sb <= lim) {
#pragma unroll
                for (int ntp = 0; ntp < 4; ntp++) {
                    uint32_t r0, r1, r2, r3;
                    LDSM4T(r0, r1, r2, r3, vB + ((sb + l15) * 72 + ntp * 16 + colb) * 2);
                    mma16816(oa[2 * ntp],     pa[kt][0], pa[kt][1], pa[kt][2], pa[kt][3], r0, r1);
                    mma16816(oa[2 * ntp + 1], pa[kt][0], pa[kt][1], pa[kt][2], pa[kt][3], r2, r3);
                }
            }
        }

        if (ch == 1) {
#pragma unroll
            for (int nt = 0; nt < 8; nt++) {
                int col = nt * 8 + tg * 2;
                *(float2*)&Osm[(wm * 16 + g) * 66 + col]     = make_float2(oa[nt][0], oa[nt][1]);
                *(float2*)&Osm[(wm * 16 + g + 8) * 66 + col] = make_float2(oa[nt][2], oa[nt][3]);
            }
        }
        __syncthreads();
        if (ch == 0) {
            __half* o1p = g_attn + (size_t)(b * TLEN + row1) * DM + h * HS;
            __half* o2p = g_attn + (size_t)(b * TLEN + row2) * DM + h * HS;
#pragma unroll
            for (int nt = 0; nt < 8; nt++) {
                int col = nt * 8 + tg * 2;
                float2 p1 = *(float2*)&Osm[(wm * 16 + g) * 66 + col];
                float2 p2 = *(float2*)&Osm[(wm * 16 + g + 8) * 66 + col];
                *(__half2*)(o1p + col) = __floats2half2_rn((oa[nt][0] + p1.x) * inv1,
                                                           (oa[nt][1] + p1.y) * inv1);
                *(__half2*)(o2p + col) = __floats2half2_rn((oa[nt][2] + p2.x) * inv2,
                                                           (oa[nt][3] + p2.y) * inv2);
            }
        }
        __syncthreads();
    }
}

// ---------------- launcher ----------------
extern "C" void kernel_launch(void* const* d_in, const int* in_sizes, int n_in,
                              void* d_out, int out_size) {
    const float* x   = (const float*)d_in[0];
    const float* Wq  = (const float*)d_in[1];
    const float* Wk  = (const float*)d_in[2];
    const float* Wv  = (const float*)d_in[3];
    const float* Wp  = (const float*)d_in[4];
    const float* bp  = (const float*)d_in[5];
    const float* W1  = (const float*)d_in[6];
    const float* b1  = (const float*)d_in[7];
    const float* W2  = (const float*)d_in[8];
    const float* b2  = (const float*)d_in[9];
    const float* g1  = (const float*)d_in[10];
    const float* be1 = (const float*)d_in[11];
    const float* g2  = (const float*)d_in[12];
    const float* be2 = (const float*)d_in[13];
    float* out = (float*)d_out;

    cudaFuncSetAttribute(attn_k, cudaFuncAttributeMaxDynamicSharedMemorySize, ATTN_SMEM);
    cudaFuncSetAttribute(gemm_k<0>, cudaFuncAttributeMaxDynamicSharedMemorySize, GEMM_SMEM);
    cudaFuncSetAttribute(gemm_k<1>, cudaFuncAttributeMaxDynamicSharedMemorySize, GEMM_SMEM);
    cudaFuncSetAttribute(gemm_k<2>, cudaFuncAttributeMaxDynamicSharedMemorySize, GEMM_SMEM);
    cudaFuncSetAttribute(gemm_k<3>, cudaFuncAttributeMaxDynamicSharedMemorySize, GEMM_SMEM);

    pack_qkv_k<<<(QKVN * DM + 255) / 256, 256>>>(Wq, Wk, Wv);                       // 0
    ln_k<0><<<MROWS / 8, 256>>>(x, g1, be1);                                        // 1
    int restN = DM * DM + FFD * DM + DM * FFD;
    pack_rest_k<<<(restN + 255) / 256, 256>>>(Wp, W1, W2);                          // 2
    gemm_k<0><<<dim3(QKVN / 128, MROWS / 256), 256, GEMM_SMEM>>>(nullptr, nullptr, nullptr); // 3
    attn_k<<<BATCHN * NH, 256, ATTN_SMEM>>>();                                      // 4
    gemm_k<1><<<dim3(DM / 128, MROWS / 256), 256, GEMM_SMEM>>>(bp, x, nullptr);     // 5
    ln_k<1><<<MROWS / 8, 256>>>(nullptr, g2, be2);                                  // 6
    gemm_k<2><<<dim3(FFD / 128, MROWS / 256), 256, GEMM_SMEM>>>(b1, nullptr, nullptr); // 7
    gemm_k<3><<<dim3(DM / 128, MROWS / 256), 256, GEMM_SMEM>>>(b2, nullptr, out);   // 8
}

// round 14
// speedup vs baseline: 1.1863x; 1.1863x over previous
#include <cuda_runtime.h>
#include <cuda_fp16.h>
#include <cstdint>

#define BATCHN 128
#define TLEN   256
#define DM     384
#define NH     6
#define HS     64
#define FFD    1536
#define MROWS  (BATCHN*TLEN)   // 32768
#define QKVN   (3*DM)          // 1152

// ---------------- scratch (device globals: allocation-free rule) ----------------
__device__ __align__(256) __half g_h   [MROWS*DM];
__device__ __align__(256) __half g_qkv [MROWS*QKVN];
__device__ __align__(256) __half g_attn[MROWS*DM];
__device__ __align__(256) float  g_x2  [MROWS*DM];     // residual kept f32
__device__ __align__(256) __half g_h2  [MROWS*DM];
__device__ __align__(256) __half g_ff1 [MROWS*FFD];
__device__ __align__(256) __half g_Wqkv[QKVN*DM];      // [n][k]
__device__ __align__(256) __half g_Wp  [DM*DM];
__device__ __align__(256) __half g_W1  [FFD*DM];
__device__ __align__(256) __half g_W2  [DM*FFD];

// ---------------- helpers ----------------
__device__ __forceinline__ uint32_t s2u(const void* p) {
    return (uint32_t)__cvta_generic_to_shared(p);
}
#define CP16(dst, src) asm volatile("cp.async.cg.shared.global [%0],[%1],16;\n" :: "r"(dst), "l"(src))
#define CPCOMMIT()     asm volatile("cp.async.commit_group;\n")
#define CPWAIT(n)      asm volatile("cp.async.wait_group %0;\n" :: "n"(n))
#define LDSM4(r0,r1,r2,r3,addr) \
    asm volatile("ldmatrix.sync.aligned.m8n8.x4.shared.b16 {%0,%1,%2,%3},[%4];" \
                 : "=r"(r0),"=r"(r1),"=r"(r2),"=r"(r3) : "r"(addr))
#define LDSM4T(r0,r1,r2,r3,addr) \
    asm volatile("ldmatrix.sync.aligned.m8n8.x4.trans.shared.b16 {%0,%1,%2,%3},[%4];" \
                 : "=r"(r0),"=r"(r1),"=r"(r2),"=r"(r3) : "r"(addr))

// f32-accum mma (attention)
__device__ __forceinline__ void mma16816(float* c, uint32_t a0, uint32_t a1,
                                         uint32_t a2, uint32_t a3,
                                         uint32_t b0, uint32_t b1) {
    asm volatile(
        "mma.sync.aligned.m16n8k16.row.col.f32.f16.f16.f32 "
        "{%0,%1,%2,%3},{%4,%5,%6,%7},{%8,%9},{%0,%1,%2,%3};\n"
        : "+f"(c[0]), "+f"(c[1]), "+f"(c[2]), "+f"(c[3])
        : "r"(a0), "r"(a1), "r"(a2), "r"(a3), "r"(b0), "r"(b1));
}

// f16-accum mma (GEMMs): C/D are 2 regs of half2; c[0] = {row g, col c0/c1}, c[1] = {row g+8}
__device__ __forceinline__ void mma16816h(uint32_t* c, uint32_t a0, uint32_t a1,
                                          uint32_t a2, uint32_t a3,
                                          uint32_t b0, uint32_t b1) {
    asm volatile(
        "mma.sync.aligned.m16n8k16.row.col.f16.f16.f16.f16 "
        "{%0,%1},{%2,%3,%4,%5},{%6,%7},{%0,%1};\n"
        : "+r"(c[0]), "+r"(c[1])
        : "r"(a0), "r"(a1), "r"(a2), "r"(a3), "r"(b0), "r"(b1));
}

// pack two floats into one u32 holding half2 (full 32 bits)
__device__ __forceinline__ uint32_t pack_h2(float a, float b) {
    __half2 h = __floats2half2_rn(a, b);
    uint32_t u;
    asm("mov.b32 %0, %1;" : "=r"(u) : "r"(*(uint32_t*)&h));
    return u;
}

// ---------------- weight packing (split: qkv first, rest second) ----------------
__global__ void pack_qkv_k(const float* __restrict__ Wq, const float* __restrict__ Wk,
                           const float* __restrict__ Wv) {
    int idx = blockIdx.x * 256 + threadIdx.x;
    if (idx >= QKVN * DM) return;
    int n = idx / DM, k = idx - n * DM;
    int part = n / DM, c = n - part * DM;
    int h = c >> 6, e = c & 63;
    const float* W = (part == 0) ? Wq : (part == 1) ? Wk : Wv;
    g_Wqkv[idx] = __float2half(W[(h * DM + k) * HS + e]);
}
__global__ void pack_rest_k(const float* __restrict__ Wp, const float* __restrict__ W1,
                            const float* __restrict__ W2) {
    int idx = blockIdx.x * 256 + threadIdx.x;
    const int n1 = DM * DM;
    const int n2 = n1 + FFD * DM;
    const int n3 = n2 + DM * FFD;
    if (idx < n1) {
        int n = idx / DM, k = idx - n * DM;
        g_Wp[idx] = __float2half(Wp[k * DM + n]);
    } else if (idx < n2) {
        int i = idx - n1;
        int n = i / DM, k = i - n * DM;
        g_W1[i] = __float2half(W1[k * FFD + n]);
    } else if (idx < n3) {
        int i = idx - n2;
        int n = i / FFD, k = i - n * FFD;
        g_W2[i] = __float2half(W2[k * DM + n]);
    }
}

// ---------------- LayerNorm: warp per row, f32 in -> half out ----------------
template <int SRC>
__global__ void __launch_bounds__(256) ln_k(const float* __restrict__ xin,
                                            const float* __restrict__ gam,
                                            const float* __restrict__ bet) {
    const float* x = (SRC == 0) ? xin : g_x2;
    __half* out = (SRC == 0) ? g_h : g_h2;
    int row = blockIdx.x * 8 + (threadIdx.x >> 5);
    int lane = threadIdx.x & 31;
    const float* xr = x + (size_t)row * DM;
    float v[12];
    float s = 0.f;
#pragma unroll
    for (int i = 0; i < 12; i++) { v[i] = xr[lane + 32 * i]; s += v[i]; }
#pragma unroll
    for (int o = 16; o; o >>= 1) s += __shfl_xor_sync(0xffffffffu, s, o);
    float mu = s * (1.f / DM);
    float var = 0.f;
#pragma unroll
    for (int i = 0; i < 12; i++) { float d = v[i] - mu; var += d * d; }
#pragma unroll
    for (int o = 16; o; o >>= 1) var += __shfl_xor_sync(0xffffffffu, var, o);
    float r = rsqrtf(var * (1.f / DM) + 1e-5f);
    __half* orow = out + (size_t)row * DM;
#pragma unroll
    for (int i = 0; i < 12; i++) {
        int c = lane + 32 * i;
        orow[c] = __float2half((v[i] - mu) * r * gam[c] + bet[c]);
    }
}

// ---------------- fp16 GEMM (f16 accum): CTA 128x128, 512 thr, warp 32x32, BK=64 ----
#define SW 72                        // smem row stride in halves (9x16B: conflict-free)
#define NSTG 3
#define STG_BYTES (128 * SW * 2)     // 18432
#define GEMM_SMEM (2 * NSTG * STG_BYTES)   // 110592

template <int CFG>
__device__ __forceinline__ void epi_store(int row, int col, float v0, float v1,
                                          const float* __restrict__ bias,
                                          const float* __restrict__ resid,
                                          float* __restrict__ outp, int N) {
    size_t o = (size_t)row * N + col;
    if (CFG == 0) {
        *(__half2*)(g_qkv + o) = __floats2half2_rn(v0, v1);
    } else if (CFG == 1) {
        float2 r = *(const float2*)(resid + o);
        *(float2*)(g_x2 + o) = make_float2(v0 + bias[col] + r.x, v1 + bias[col + 1] + r.y);
    } else if (CFG == 2) {
        *(__half2*)(g_ff1 + o) = __floats2half2_rn(fmaxf(v0 + bias[col], 0.f),
                                                   fmaxf(v1 + bias[col + 1], 0.f));
    } else {
        float2 r = *(const float2*)(g_x2 + o);
        *(float2*)(outp + o) = make_float2(v0 + bias[col] + r.x, v1 + bias[col + 1] + r.y);
    }
}

template <int CFG>
__global__ void __launch_bounds__(512, 2)
gemm_k(const float* __restrict__ bias, const float* __restrict__ resid,
       float* __restrict__ outp) {
    constexpr int N = (CFG == 0) ? QKVN : (CFG == 2) ? FFD : DM;
    constexpr int K = (CFG == 3) ? FFD : DM;
    constexpr int NT = K / 64;       // 6 or 24
    const __half* __restrict__ A = (CFG == 0) ? g_h : (CFG == 1) ? g_attn
                                 : (CFG == 2) ? g_h2 : g_ff1;
    const __half* __restrict__ W = (CFG == 0) ? g_Wqkv : (CFG == 1) ? g_Wp
                                 : (CFG == 2) ? g_W1 : g_W2;

    extern __shared__ __half sm[];
    uint32_t aBase = s2u(sm);
    uint32_t wBase = aBase + NSTG * STG_BYTES;

    int tid = threadIdx.x;
    int lane = tid & 31, wid = tid >> 5;      // wid 0..15
    int wm = wid & 3, wn = wid >> 2;          // 4 warps along M, 4 along N
    int m0 = blockIdx.y * 128, n0 = blockIdx.x * 128;

    auto LOAD = [&](int kt) {
        int st = kt % NSTG;
        uint32_t aS = aBase + st * STG_BYTES;
        uint32_t bS = wBase + st * STG_BYTES;
#pragma unroll
        for (int i = 0; i < 2; i++) {
            int c = tid + 512 * i;            // 1024 chunks of 16B per operand
            int row = c >> 3, col = (c & 7) * 8;
            uint32_t off = (uint32_t)(row * SW + col) * 2;
            CP16(aS + off, A + (size_t)(m0 + row) * K + kt * 64 + col);
            CP16(bS + off, W + (size_t)(n0 + row) * K + kt * 64 + col);
        }
        CPCOMMIT();
    };

    uint32_t acc[2][4][2];                    // f16x2 accumulators
#pragma unroll
    for (int a = 0; a < 2; a++)
#pragma unroll
        for (int b = 0; b < 4; b++) { acc[a][b][0] = 0u; acc[a][b][1] = 0u; }

    LOAD(0);
    LOAD(1);

    int l15 = lane & 15;
    int colb = (lane >> 4) * 8;

    for (int kt = 0; kt < NT; kt++) {
        if (kt < NT - 1) { CPWAIT(1); } else { CPWAIT(0); }
        __syncthreads();
        if (kt + 2 < NT) LOAD(kt + 2);

        uint32_t aS = aBase + (kt % NSTG) * STG_BYTES;
        uint32_t wS = wBase + (kt % NSTG) * STG_BYTES;
#pragma unroll
        for (int kk = 0; kk < 64; kk += 16) {
            uint32_t af[2][4], bf[4][2];
#pragma unroll
            for (int mt = 0; mt < 2; mt++) {
                int r = wm * 32 + mt * 16 + l15;
                LDSM4(af[mt][0], af[mt][1], af[mt][2], af[mt][3],
                      aS + (r * SW + kk + colb) * 2);
            }
#pragma unroll
            for (int np = 0; np < 2; np++) {
                uint32_t r0, r1, r2, r3;
                int r = wn * 32 + np * 16 + l15;
                LDSM4(r0, r1, r2, r3, wS + (r * SW + kk + colb) * 2);
                bf[2 * np][0] = r0; bf[2 * np + 1][0] = r1;
                bf[2 * np][1] = r2; bf[2 * np + 1][1] = r3;
            }
#pragma unroll
            for (int mt = 0; mt < 2; mt++)
#pragma unroll
                for (int nt = 0; nt < 4; nt++)
                    mma16816h(acc[mt][nt], af[mt][0], af[mt][1], af[mt][2], af[mt][3],
                              bf[nt][0], bf[nt][1]);
        }
    }

    int g = lane >> 2, tg = lane & 3;
#pragma unroll
    for (int mt = 0; mt < 2; mt++)
#pragma unroll
        for (int nt = 0; nt < 4; nt++) {
            int row = m0 + wm * 32 + mt * 16 + g;
            int col = n0 + wn * 32 + nt * 8 + tg * 2;
            float2 p0 = __half22float2(*(__half2*)&acc[mt][nt][0]);   // row g
            float2 p1 = __half22float2(*(__half2*)&acc[mt][nt][1]);   // row g+8
            epi_store<CFG>(row, col, p0.x, p0.y, bias, resid, outp, N);
            epi_store<CFG>(row + 8, col, p1.x, p1.y, bias, resid, outp, N);
        }
}

// ---------------- attention: mma-based flash-style (R8 passing version) ----------------
#define AS_V (256*72)
#define AS_Q (AS_V + 256*72)
#define AS_HALVES (AS_Q + 64*72)
#define AS_OSM (AS_HALVES * 2)
#define AS_SM  (AS_OSM + 4*16*66*4)
#define AS_SS  (AS_SM + 512)
#define ATTN_SMEM (AS_SS + 512)            // 100864

__global__ void __launch_bounds__(256, 2) attn_k() {
    extern __shared__ unsigned char smraw[];
    __half* sK = (__half*)smraw;
    __half* sV = sK + AS_V;
    __half* sQ = sK + AS_Q;
    float* Osm = (float*)(smraw + AS_OSM);
    float* sM  = (float*)(smraw + AS_SM);
    float* sS  = (float*)(smraw + AS_SS);

    int bh = blockIdx.x;
    int b = bh / NH, h = bh - b * NH;
    int tid = threadIdx.x, wid = tid >> 5, lane = tid & 31;
    int wm = wid & 3, ch = wid >> 2;
    int g = lane >> 2, tg = lane & 3;
    int l15 = lane & 15;
    int colb = (lane >> 4) * 8;
    const __half* base = g_qkv + (size_t)b * TLEN * QKVN;

    for (int i = tid; i < TLEN * 32; i += 256) {
        int s = i >> 5, e2 = i & 31;
        ((__half2*)sK)[s * 36 + e2] =
            *(const __half2*)(base + (size_t)s * QKVN + DM + h * HS + 2 * e2);
        ((__half2*)sV)[s * 36 + e2] =
            *(const __half2*)(base + (size_t)s * QKVN + 2 * DM + h * HS + 2 * e2);
    }
    __syncthreads();

    uint32_t kB = s2u(sK), vB = s2u(sV), qB = s2u(sQ);
    const __half2 qscale = __floats2half2_rn(0.125f, 0.125f);
    int stIdx = (ch * 4 + wm) * 16;
    int stOth = ((1 - ch) * 4 + wm) * 16;

    for (int iq = 0; iq < 4; iq++) {
        int tq = iq * 64;
        for (int i = tid; i < 64 * 32; i += 256) {
            int r = i >> 5, e2 = i & 31;
            __half2 q2 = *(const __half2*)(base + (size_t)(tq + r) * QKVN + h * HS + 2 * e2);
            ((__half2*)sQ)[r * 36 + e2] = __hmul2(q2, qscale);
        }
        __syncthreads();

        int lim = tq + wm * 16 + 15;
        int row1 = tq + wm * 16 + g, row2 = row1 + 8;

        float acc[16][4];
#pragma unroll
        for (int nt = 0; nt < 16; nt++)
#pragma unroll
            for (int c = 0; c < 4; c++) acc[nt][c] = 0.f;

#pragma unroll
        for (int kt = 0; kt < 4; kt++) {
            uint32_t a0, a1, a2, a3;
            LDSM4(a0, a1, a2, a3, qB + ((wm * 16 + l15) * 72 + kt * 16 + colb) * 2);
#pragma unroll
            for (int ntp = 0; ntp < 8; ntp++) {
                int nb = ch * 128 + ntp * 16;
                if (nb <= lim) {
                    uint32_t r0, r1, r2, r3;
                    LDSM4(r0, r1, r2, r3, kB + ((nb + l15) * 72 + kt * 16 + colb) * 2);
                    mma16816(acc[2 * ntp],     a0, a1, a2, a3, r0, r2);
                    mma16816(acc[2 * ntp + 1], a0, a1, a2, a3, r1, r3);
                }
            }
        }

#pragma unroll
        for (int nt = 0; nt < 16; nt++) {
            int c0 = ch * 128 + nt * 8 + tg * 2;
            if (c0 > row1)     acc[nt][0] = -1e30f;
            if (c0 + 1 > row1) acc[nt][1] = -1e30f;
            if (c0 > row2)     acc[nt][2] = -1e30f;
            if (c0 + 1 > row2) acc[nt][3] = -1e30f;
        }

        float m1 = -1e30f, m2 = -1e30f;
#pragma unroll
        for (int nt = 0; nt < 16; nt++) {
            m1 = fmaxf(m1, fmaxf(acc[nt][0], acc[nt][1]));
            m2 = fmaxf(m2, fmaxf(acc[nt][2], acc[nt][3]));
        }
        m1 = fmaxf(m1, __shfl_xor_sync(0xffffffffu, m1, 1));
        m1 = fmaxf(m1, __shfl_xor_sync(0xffffffffu, m1, 2));
        m2 = fmaxf(m2, __shfl_xor_sync(0xffffffffu, m2, 1));
        m2 = fmaxf(m2, __shfl_xor_sync(0xffffffffu, m2, 2));
        if (tg == 0) { sM[stIdx + g] = m1; sM[stIdx + g + 8] = m2; }
        __syncthreads();
        float M1 = fmaxf(m1, sM[stOth + g]);
        float M2 = fmaxf(m2, sM[stOth + g + 8]);

        float s1 = 0.f, s2 = 0.f;
#pragma unroll
        for (int nt = 0; nt < 16; nt++) {
            acc[nt][0] = __expf(acc[nt][0] - M1);
            acc[nt][1] = __expf(acc[nt][1] - M1);
            acc[nt][2] = __expf(acc[nt][2] - M2);
            acc[nt][3] = __expf(acc[nt][3] - M2);
            s1 += acc[nt][0] + acc[nt][1];
            s2 += acc[nt][2] + acc[nt][3];
        }
        s1 += __shfl_xor_sync(0xffffffffu, s1, 1);
        s1 += __shfl_xor_sync(0xffffffffu, s1, 2);
        s2 += __shfl_xor_sync(0xffffffffu, s2, 1);
        s2 += __shfl_xor_sync(0xffffffffu, s2, 2);
        if (tg == 0) { sS[stIdx + g] = s1; sS[stIdx + g + 8] = s2; }
        __syncthreads();
        float inv1 = 1.f / (s1 + sS[stOth + g]);
        float inv2 = 1.f / (s2 + sS[stOth + g + 8]);

        uint32_t pa[8][4];
#pragma unroll
        for (int kt = 0; kt < 8; kt++) {
            pa[kt][0] = pack_h2(acc[2 * kt][0],     acc[2 * kt][1]);
            pa[kt][1] = pack_h2(acc[2 * kt][2],     acc[2 * kt][3]);
            pa[kt][2] = pack_h2(acc[2 * kt + 1][0], acc[2 * kt + 1][1]);
            pa[kt][3] = pack_h2(acc[2 * kt + 1][2], acc[2 * kt + 1][3]);
        }

        float oa[8][4];
#pragma unroll
        for (int nt = 0; nt < 8; nt++)
#pragma unroll
            for (int c = 0; c < 4; c++) oa[nt][c] = 0.f;

#pragma unroll
        for (int kt = 0; kt < 8; kt++) {
            int sb = ch * 128 + kt * 16;
            if (sb <= lim) {
#pragma unroll
                for (int ntp = 0; ntp < 4; ntp++) {
                    uint32_t r0, r1, r2, r3;
                    LDSM4T(r0, r1, r2, r3, vB + ((sb + l15) * 72 + ntp * 16 + colb) * 2);
                    mma16816(oa[2 * ntp],     pa[kt][0], pa[kt][1], pa[kt][2], pa[kt][3], r0, r1);
                    mma16816(oa[2 * ntp + 1], pa[kt][0], pa[kt][1], pa[kt][2], pa[kt][3], r2, r3);
                }
            }
        }

        if (ch == 1) {
#pragma unroll
            for (int nt = 0; nt < 8; nt++) {
                int col = nt * 8 + tg * 2;
                *(float2*)&Osm[(wm * 16 + g) * 66 + col]     = make_float2(oa[nt][0], oa[nt][1]);
                *(float2*)&Osm[(wm * 16 + g + 8) * 66 + col] = make_float2(oa[nt][2], oa[nt][3]);
            }
        }
        __syncthreads();
        if (ch == 0) {
            __half* o1p = g_attn + (size_t)(b * TLEN + row1) * DM + h * HS;
            __half* o2p = g_attn + (size_t)(b * TLEN + row2) * DM + h * HS;
#pragma unroll
            for (int nt = 0; nt < 8; nt++) {
                int col = nt * 8 + tg * 2;
                float2 p1 = *(float2*)&Osm[(wm * 16 + g) * 66 + col];
                float2 p2 = *(float2*)&Osm[(wm * 16 + g + 8) * 66 + col];
                *(__half2*)(o1p + col) = __floats2half2_rn((oa[nt][0] + p1.x) * inv1,
                                                           (oa[nt][1] + p1.y) * inv1);
                *(__half2*)(o2p + col) = __floats2half2_rn((oa[nt][2] + p2.x) * inv2,
                                                           (oa[nt][3] + p2.y) * inv2);
            }
        }
        __syncthreads();
    }
}

// ---------------- launcher ----------------
extern "C" void kernel_launch(void* const* d_in, const int* in_sizes, int n_in,
                              void* d_out, int out_size) {
    const float* x   = (const float*)d_in[0];
    const float* Wq  = (const float*)d_in[1];
    const float* Wk  = (const float*)d_in[2];
    const float* Wv  = (const float*)d_in[3];
    const float* Wp  = (const float*)d_in[4];
    const float* bp  = (const float*)d_in[5];
    const float* W1  = (const float*)d_in[6];
    const float* b1  = (const float*)d_in[7];
    const float* W2  = (const float*)d_in[8];
    const float* b2  = (const float*)d_in[9];
    const float* g1  = (const float*)d_in[10];
    const float* be1 = (const float*)d_in[11];
    const float* g2  = (const float*)d_in[12];
    const float* be2 = (const float*)d_in[13];
    float* out = (float*)d_out;

    cudaFuncSetAttribute(attn_k, cudaFuncAttributeMaxDynamicSharedMemorySize, ATTN_SMEM);
    cudaFuncSetAttribute(gemm_k<0>, cudaFuncAttributeMaxDynamicSharedMemorySize, GEMM_SMEM);
    cudaFuncSetAttribute(gemm_k<1>, cudaFuncAttributeMaxDynamicSharedMemorySize, GEMM_SMEM);
    cudaFuncSetAttribute(gemm_k<2>, cudaFuncAttributeMaxDynamicSharedMemorySize, GEMM_SMEM);
    cudaFuncSetAttribute(gemm_k<3>, cudaFuncAttributeMaxDynamicSharedMemorySize, GEMM_SMEM);

    pack_qkv_k<<<(QKVN * DM + 255) / 256, 256>>>(Wq, Wk, Wv);                       // 0
    ln_k<0><<<MROWS / 8, 256>>>(x, g1, be1);                                        // 1
    int restN = DM * DM + FFD * DM + DM * FFD;
    pack_rest_k<<<(restN + 255) / 256, 256>>>(Wp, W1, W2);                          // 2
    gemm_k<0><<<dim3(QKVN / 128, MROWS / 128), 512, GEMM_SMEM>>>(nullptr, nullptr, nullptr); // 3
    attn_k<<<BATCHN * NH, 256, ATTN_SMEM>>>();                                      // 4
    gemm_k<1><<<dim3(DM / 128, MROWS / 128), 512, GEMM_SMEM>>>(bp, x, nullptr);     // 5
    ln_k<1><<<MROWS / 8, 256>>>(nullptr, g2, be2);                                  // 6
    gemm_k<2><<<dim3(FFD / 128, MROWS / 128), 512, GEMM_SMEM>>>(b1, nullptr, nullptr); // 7
    gemm_k<3><<<dim3(DM / 128, MROWS / 128), 512, GEMM_SMEM>>>(b2, nullptr, out);   // 8
}